// round 2
// baseline (speedup 1.0000x reference)
#include <cuda_runtime.h>

#define CELLS_PER_BLOCK 128
#define THREADS 128
#define MAX_BLOCKS 4096

__device__ float        g_partials[MAX_BLOCKS];
__device__ unsigned int g_ticket = 0;

__global__ void __launch_bounds__(THREADS) yolo_loss_kernel(
    const float* __restrict__ pred,
    const float* __restrict__ targ,
    int total_cells, int nchunks, float inv_n,
    float* __restrict__ out)
{
    __shared__ float sp[CELLS_PER_BLOCK * 30];
    __shared__ float st[CELLS_PER_BLOCK * 30];
    __shared__ float warpsum[THREADS / 32];
    __shared__ bool  am_last;

    const int tid = threadIdx.x;
    float acc = 0.0f;

    for (int chunk = blockIdx.x; chunk < nchunks; chunk += gridDim.x) {
        const int cell0 = chunk * CELLS_PER_BLOCK;
        const int cells_here = min(CELLS_PER_BLOCK, total_cells - cell0);
        const long long base = (long long)cell0 * 30;
        const int nfloat = cells_here * 30;
        const int nvec = nfloat >> 2;

        const float4* p4 = reinterpret_cast<const float4*>(pred + base);
        const float4* t4 = reinterpret_cast<const float4*>(targ + base);
        float4* sp4 = reinterpret_cast<float4*>(sp);
        float4* st4 = reinterpret_cast<float4*>(st);

        __syncthreads();   // protect smem reuse across chunk iterations

        // Front-batched staging: 8 outstanding LDG.128 per round, then STS.
        #pragma unroll
        for (int r = 0; r < 2; r++) {
            float4 rp[4], rt[4];
            #pragma unroll
            for (int k = 0; k < 4; k++) {
                const int i = tid + (r * 4 + k) * THREADS;
                if (i < nvec) { rp[k] = __ldcs(p4 + i); rt[k] = __ldcs(t4 + i); }
            }
            #pragma unroll
            for (int k = 0; k < 4; k++) {
                const int i = tid + (r * 4 + k) * THREADS;
                if (i < nvec) { sp4[i] = rp[k]; st4[i] = rt[k]; }
            }
        }
        // scalar tail (ragged last chunk only; never hit for the given shape)
        for (int i = (nvec << 2) + tid; i < nfloat; i += THREADS) {
            sp[i] = pred[base + i];
            st[i] = targ[base + i];
        }
        __syncthreads();

        if (tid < cells_here) {
            const float* P = sp + tid * 30;
            const float* T = st + tid * 30;
            const float inv14 = 1.0f / 14.0f;

            const float conf_t = T[4];
            const float coo = (conf_t > 0.0f) ? 1.0f : 0.0f;
            const float noo = (conf_t == 0.0f) ? 1.0f : 0.0f;

            const float tcx = T[0] * inv14;
            const float tcy = T[1] * inv14;
            const float tx1 = tcx - 0.5f * T[2];
            const float ty1 = tcy - 0.5f * T[3];
            const float tx2 = tcx + 0.5f * T[2];
            const float ty2 = tcy + 0.5f * T[3];
            const float ta = (tx2 - tx1) * (ty2 - ty1);

            float iou[2], bx[2], by[2], bw[2], bh[2], bc[2];
            #pragma unroll
            for (int b = 0; b < 2; b++) {
                const float* B = P + b * 5;
                bx[b] = B[0]; by[b] = B[1]; bw[b] = B[2]; bh[b] = B[3]; bc[b] = B[4];
                const float pcx = B[0] * inv14;
                const float pcy = B[1] * inv14;
                const float px1 = pcx - 0.5f * B[2];
                const float py1 = pcy - 0.5f * B[3];
                const float px2 = pcx + 0.5f * B[2];
                const float py2 = pcy + 0.5f * B[3];
                const float ltx = fmaxf(px1, tx1);
                const float lty = fmaxf(py1, ty1);
                const float rbx = fminf(px2, tx2);
                const float rby = fminf(py2, ty2);
                const float w = fmaxf(rbx - ltx, 0.0f);
                const float h = fmaxf(rby - lty, 0.0f);
                const float inter = w * h;
                const float pa = (px2 - px1) * (py2 - py1);
                iou[b] = inter / (pa + ta - inter);
            }

            const int r = (iou[1] > iou[0]) ? 1 : 0;   // argmax: first max wins
            const int nr = 1 - r;
            const float max_iou = iou[r];

            const float dx = bx[r] - T[0];
            const float dy = by[r] - T[1];
            const float dsw = sqrtf(bw[r]) - sqrtf(T[2]);
            const float dsh = sqrtf(bh[r]) - sqrtf(T[3]);
            const float loc = dx * dx + dy * dy + dsw * dsw + dsh * dsh;

            const float dcc = bc[r] - max_iou;
            const float contain = dcc * dcc;
            const float ncl = bc[nr] * bc[nr];

            const float d4 = P[4] - T[4];
            const float d9 = P[9] - T[9];
            const float noobj = d4 * d4 + d9 * d9;

            float cls = 0.0f;
            #pragma unroll
            for (int k = 10; k < 30; k++) {
                const float d = P[k] - T[k];
                cls += d * d;
            }

            acc += coo * (5.0f * loc + 2.0f * contain + ncl + cls)
                 + 0.5f * noo * noobj;
        }
    }

    // block reduction of acc
    #pragma unroll
    for (int o = 16; o > 0; o >>= 1)
        acc += __shfl_down_sync(0xffffffffu, acc, o);
    if ((tid & 31) == 0) warpsum[tid >> 5] = acc;
    __syncthreads();
    if (tid == 0) {
        float s = 0.0f;
        #pragma unroll
        for (int w = 0; w < THREADS / 32; w++) s += warpsum[w];
        g_partials[blockIdx.x] = s;
        __threadfence();
        const unsigned t = atomicAdd(&g_ticket, 1u);
        am_last = (t == gridDim.x - 1);
    }
    __syncthreads();

    // last block reduces all partials in fixed order (deterministic)
    if (am_last) {
        float s = 0.0f;
        for (int i = tid; i < (int)gridDim.x; i += THREADS)
            s += __ldcg(&g_partials[i]);
        #pragma unroll
        for (int o = 16; o > 0; o >>= 1)
            s += __shfl_down_sync(0xffffffffu, s, o);
        if ((tid & 31) == 0) warpsum[tid >> 5] = s;
        __syncthreads();
        if (tid == 0) {
            float tot = 0.0f;
            #pragma unroll
            for (int w = 0; w < THREADS / 32; w++) tot += warpsum[w];
            out[0] = tot * inv_n;
            g_ticket = 0;          // reset for next graph replay
        }
    }
}

extern "C" void kernel_launch(void* const* d_in, const int* in_sizes, int n_in,
                              void* d_out, int out_size)
{
    const float* pred = (const float*)d_in[0];
    const float* targ = (const float*)d_in[1];
    const int total = in_sizes[0];              // N*14*14*30
    const int cells = total / 30;
    const int N = cells / 196;
    const int nchunks = (cells + CELLS_PER_BLOCK - 1) / CELLS_PER_BLOCK;

    int grid = 148 * 7;                          // persistent-ish
    if (grid > nchunks) grid = nchunks;
    if (grid > MAX_BLOCKS) grid = MAX_BLOCKS;

    yolo_loss_kernel<<<grid, THREADS>>>(pred, targ, cells, nchunks,
                                        1.0f / (float)N, (float*)d_out);
}

// round 3
// speedup vs baseline: 1.2636x; 1.2636x over previous
#include <cuda_runtime.h>

#define THREADS 128
#define CPB 128                               // cells per chunk
#define FLOATS_PER_CHUNK (CPB * 30)           // 3840
#define VEC_PER_CHUNK (FLOATS_PER_CHUNK / 4)  // 960 float4 per tensor
#define STAGE_FLOATS (2 * FLOATS_PER_CHUNK)   // pred + targ = 7680 floats = 30720 B
#define NSTAGES 2
#define SMEM_BYTES (NSTAGES * STAGE_FLOATS * 4)  // 61440
#define MAX_BLOCKS 4096

__device__ float        g_partials[MAX_BLOCKS];
__device__ unsigned int g_ticket = 0;

extern __shared__ float smem_buf[];

__device__ __forceinline__ void cp16(float* dst, const float4* src) {
    unsigned s = (unsigned)__cvta_generic_to_shared(dst);
    asm volatile("cp.async.cg.shared.global [%0], [%1], 16;" :: "r"(s), "l"(src));
}

// Issue async copies for one full chunk into a stage buffer.
// Layout inside stage: floats [0, 3840) = pred cells, [3840, 7680) = targ cells.
__device__ __forceinline__ void issue_chunk(float* stage,
                                            const float4* __restrict__ pred4,
                                            const float4* __restrict__ targ4,
                                            long long chunk, int tid)
{
    const float4* pb = pred4 + chunk * VEC_PER_CHUNK;
    const float4* tb = targ4 + chunk * VEC_PER_CHUNK;
    #pragma unroll
    for (int m = 0; m < 15; m++) {
        const int idx = tid + m * THREADS;  // 0..1919, exact cover
        const float4* src = (idx < VEC_PER_CHUNK) ? (pb + idx)
                                                  : (tb + (idx - VEC_PER_CHUNK));
        cp16(stage + idx * 4, src);
    }
}

__device__ __forceinline__ float cell_loss(const float* __restrict__ P,
                                           const float* __restrict__ T)
{
    const float inv14 = 1.0f / 14.0f;

    const float conf_t = T[4];
    const float coo = (conf_t > 0.0f) ? 1.0f : 0.0f;
    const float noo = (conf_t == 0.0f) ? 1.0f : 0.0f;

    const float tcx = T[0] * inv14;
    const float tcy = T[1] * inv14;
    const float tx1 = tcx - 0.5f * T[2];
    const float ty1 = tcy - 0.5f * T[3];
    const float tx2 = tcx + 0.5f * T[2];
    const float ty2 = tcy + 0.5f * T[3];
    const float ta = (tx2 - tx1) * (ty2 - ty1);

    float iou[2], bx[2], by[2], bw[2], bh[2], bc[2];
    #pragma unroll
    for (int b = 0; b < 2; b++) {
        const float* B = P + b * 5;
        bx[b] = B[0]; by[b] = B[1]; bw[b] = B[2]; bh[b] = B[3]; bc[b] = B[4];
        const float pcx = B[0] * inv14;
        const float pcy = B[1] * inv14;
        const float px1 = pcx - 0.5f * B[2];
        const float py1 = pcy - 0.5f * B[3];
        const float px2 = pcx + 0.5f * B[2];
        const float py2 = pcy + 0.5f * B[3];
        const float ltx = fmaxf(px1, tx1);
        const float lty = fmaxf(py1, ty1);
        const float rbx = fminf(px2, tx2);
        const float rby = fminf(py2, ty2);
        const float w = fmaxf(rbx - ltx, 0.0f);
        const float h = fmaxf(rby - lty, 0.0f);
        const float inter = w * h;
        const float pa = (px2 - px1) * (py2 - py1);
        iou[b] = __fdividef(inter, pa + ta - inter);
    }

    const int r = (iou[1] > iou[0]) ? 1 : 0;   // argmax: first max wins
    const int nr = 1 - r;
    const float max_iou = iou[r];

    const float dx = bx[r] - T[0];
    const float dy = by[r] - T[1];
    const float dsw = sqrtf(bw[r]) - sqrtf(T[2]);
    const float dsh = sqrtf(bh[r]) - sqrtf(T[3]);
    const float loc = dx * dx + dy * dy + dsw * dsw + dsh * dsh;

    const float dcc = bc[r] - max_iou;
    const float contain = dcc * dcc;
    const float ncl = bc[nr] * bc[nr];

    const float d4 = P[4] - T[4];
    const float d9 = P[9] - T[9];
    const float noobj = d4 * d4 + d9 * d9;

    float cls = 0.0f;
    #pragma unroll
    for (int k = 10; k < 30; k++) {
        const float d = P[k] - T[k];
        cls += d * d;
    }

    return coo * (5.0f * loc + 2.0f * contain + ncl + cls)
         + 0.5f * noo * noobj;
}

__global__ void __launch_bounds__(THREADS) yolo_loss_kernel(
    const float* __restrict__ pred,
    const float* __restrict__ targ,
    int nfull, int rem, float inv_n,
    float* __restrict__ out)
{
    __shared__ float warpsum[THREADS / 32];
    __shared__ bool  am_last;

    const int tid = threadIdx.x;
    const float4* pred4 = reinterpret_cast<const float4*>(pred);
    const float4* targ4 = reinterpret_cast<const float4*>(targ);

    float acc = 0.0f;

    long long c = blockIdx.x;
    if (c < nfull) {
        issue_chunk(smem_buf, pred4, targ4, c, tid);
        asm volatile("cp.async.commit_group;");

        int it = 0;
        while (true) {
            const int cur = it & 1;
            const long long cn = c + gridDim.x;
            const bool have_next = (cn < nfull);
            if (have_next) {
                issue_chunk(smem_buf + (1 - cur) * STAGE_FLOATS, pred4, targ4, cn, tid);
                asm volatile("cp.async.commit_group;");
                asm volatile("cp.async.wait_group 1;");
            } else {
                asm volatile("cp.async.wait_group 0;");
            }
            __syncthreads();   // stage 'cur' fully visible to all threads

            const float* stage = smem_buf + cur * STAGE_FLOATS;
            acc += cell_loss(stage + tid * 30,
                             stage + FLOATS_PER_CHUNK + tid * 30);

            __syncthreads();   // done reading 'cur' before it is refilled
            if (!have_next) break;
            c = cn; it++;
        }
    }

    // ragged tail (not hit for the benchmark shape): block 0, direct global reads
    if (rem > 0 && blockIdx.x == 0 && tid < rem) {
        const long long cell = (long long)nfull * CPB + tid;
        float Pl[30], Tl[30];
        #pragma unroll
        for (int k = 0; k < 30; k++) {
            Pl[k] = __ldg(pred + cell * 30 + k);
            Tl[k] = __ldg(targ + cell * 30 + k);
        }
        acc += cell_loss(Pl, Tl);
    }

    // block reduction
    #pragma unroll
    for (int o = 16; o > 0; o >>= 1)
        acc += __shfl_down_sync(0xffffffffu, acc, o);
    if ((tid & 31) == 0) warpsum[tid >> 5] = acc;
    __syncthreads();
    if (tid == 0) {
        float s = 0.0f;
        #pragma unroll
        for (int w = 0; w < THREADS / 32; w++) s += warpsum[w];
        g_partials[blockIdx.x] = s;
        __threadfence();
        const unsigned t = atomicAdd(&g_ticket, 1u);
        am_last = (t == gridDim.x - 1);
    }
    __syncthreads();

    // last block reduces all partials in fixed order (deterministic)
    if (am_last) {
        float s = 0.0f;
        for (int i = tid; i < (int)gridDim.x; i += THREADS)
            s += __ldcg(&g_partials[i]);
        #pragma unroll
        for (int o = 16; o > 0; o >>= 1)
            s += __shfl_down_sync(0xffffffffu, s, o);
        if ((tid & 31) == 0) warpsum[tid >> 5] = s;
        __syncthreads();
        if (tid == 0) {
            float tot = 0.0f;
            #pragma unroll
            for (int w = 0; w < THREADS / 32; w++) tot += warpsum[w];
            out[0] = tot * inv_n;
            g_ticket = 0;   // reset for next graph replay
        }
    }
}

extern "C" void kernel_launch(void* const* d_in, const int* in_sizes, int n_in,
                              void* d_out, int out_size)
{
    const float* pred = (const float*)d_in[0];
    const float* targ = (const float*)d_in[1];
    const int total = in_sizes[0];   // N*14*14*30
    const int cells = total / 30;
    const int N = cells / 196;
    const int nfull = cells / CPB;
    const int rem = cells % CPB;

    cudaFuncSetAttribute(yolo_loss_kernel,
                         cudaFuncAttributeMaxDynamicSharedMemorySize, SMEM_BYTES);

    int grid = 148 * 3;              // 3 blocks/SM (smem-limited)
    if (grid > nfull) grid = (nfull > 0) ? nfull : 1;
    if (grid > MAX_BLOCKS) grid = MAX_BLOCKS;

    yolo_loss_kernel<<<grid, THREADS, SMEM_BYTES>>>(pred, targ, nfull, rem,
                                                    1.0f / (float)N,
                                                    (float*)d_out);
}

// round 4
// speedup vs baseline: 1.2795x; 1.0126x over previous
#include <cuda_runtime.h>

#define THREADS 128
#define CPB 128                               // cells per chunk
#define FLOATS_PER_CHUNK (CPB * 30)           // 3840
#define VEC_PER_CHUNK (FLOATS_PER_CHUNK / 4)  // 960 float4 per tensor
#define STAGE_FLOATS (2 * FLOATS_PER_CHUNK)   // pred + targ = 7680 floats = 30720 B
#define NSTAGES 3
#define SMEM_BYTES (NSTAGES * STAGE_FLOATS * 4)  // 92160
#define MAX_BLOCKS 4096

__device__ float        g_partials[MAX_BLOCKS];
__device__ unsigned int g_ticket = 0;

extern __shared__ float smem_buf[];

__device__ __forceinline__ void cp16(float* dst, const float4* src) {
    unsigned s = (unsigned)__cvta_generic_to_shared(dst);
    asm volatile("cp.async.cg.shared.global [%0], [%1], 16;" :: "r"(s), "l"(src));
}

// Issue async copies for one full chunk into a stage buffer.
// Stage layout: floats [0, 3840) = pred cells, [3840, 7680) = targ cells.
__device__ __forceinline__ void issue_chunk(float* stage,
                                            const float4* __restrict__ pred4,
                                            const float4* __restrict__ targ4,
                                            long long chunk, int tid)
{
    const float4* pb = pred4 + chunk * VEC_PER_CHUNK;
    const float4* tb = targ4 + chunk * VEC_PER_CHUNK;
    #pragma unroll
    for (int m = 0; m < 15; m++) {
        const int idx = tid + m * THREADS;  // 0..1919 exact cover
        const float4* src = (idx < VEC_PER_CHUNK) ? (pb + idx)
                                                  : (tb + (idx - VEC_PER_CHUNK));
        cp16(stage + idx * 4, src);
    }
    asm volatile("cp.async.commit_group;");
}

__device__ __forceinline__ float cell_loss(const float* __restrict__ P,
                                           const float* __restrict__ T)
{
    const float inv14 = 1.0f / 14.0f;

    const float conf_t = T[4];
    const float coo = (conf_t > 0.0f) ? 1.0f : 0.0f;
    const float noo = (conf_t == 0.0f) ? 1.0f : 0.0f;

    const float tcx = T[0] * inv14;
    const float tcy = T[1] * inv14;
    const float tx1 = tcx - 0.5f * T[2];
    const float ty1 = tcy - 0.5f * T[3];
    const float tx2 = tcx + 0.5f * T[2];
    const float ty2 = tcy + 0.5f * T[3];
    const float ta = (tx2 - tx1) * (ty2 - ty1);

    float iou[2], bx[2], by[2], bw[2], bh[2], bc[2];
    #pragma unroll
    for (int b = 0; b < 2; b++) {
        const float* B = P + b * 5;
        bx[b] = B[0]; by[b] = B[1]; bw[b] = B[2]; bh[b] = B[3]; bc[b] = B[4];
        const float pcx = B[0] * inv14;
        const float pcy = B[1] * inv14;
        const float px1 = pcx - 0.5f * B[2];
        const float py1 = pcy - 0.5f * B[3];
        const float px2 = pcx + 0.5f * B[2];
        const float py2 = pcy + 0.5f * B[3];
        const float ltx = fmaxf(px1, tx1);
        const float lty = fmaxf(py1, ty1);
        const float rbx = fminf(px2, tx2);
        const float rby = fminf(py2, ty2);
        const float w = fmaxf(rbx - ltx, 0.0f);
        const float h = fmaxf(rby - lty, 0.0f);
        const float inter = w * h;
        const float pa = (px2 - px1) * (py2 - py1);
        iou[b] = __fdividef(inter, pa + ta - inter);
    }

    const int r = (iou[1] > iou[0]) ? 1 : 0;   // argmax: first max wins
    const int nr = 1 - r;
    const float max_iou = iou[r];

    const float dx = bx[r] - T[0];
    const float dy = by[r] - T[1];
    const float dsw = sqrtf(bw[r]) - sqrtf(T[2]);
    const float dsh = sqrtf(bh[r]) - sqrtf(T[3]);
    const float loc = dx * dx + dy * dy + dsw * dsw + dsh * dsh;

    const float dcc = bc[r] - max_iou;
    const float contain = dcc * dcc;
    const float ncl = bc[nr] * bc[nr];

    const float d4 = P[4] - T[4];
    const float d9 = P[9] - T[9];
    const float noobj = d4 * d4 + d9 * d9;

    float cls = 0.0f;
    #pragma unroll
    for (int k = 10; k < 30; k++) {
        const float d = P[k] - T[k];
        cls += d * d;
    }

    return coo * (5.0f * loc + 2.0f * contain + ncl + cls)
         + 0.5f * noo * noobj;
}

__global__ void __launch_bounds__(THREADS) yolo_loss_kernel(
    const float* __restrict__ pred,
    const float* __restrict__ targ,
    int nfull, int rem, float inv_n,
    float* __restrict__ out)
{
    __shared__ float warpsum[THREADS / 32];
    __shared__ bool  am_last;

    const int tid = threadIdx.x;
    const long long G = gridDim.x;
    const float4* pred4 = reinterpret_cast<const float4*>(pred);
    const float4* targ4 = reinterpret_cast<const float4*>(targ);

    float acc = 0.0f;

    long long c = blockIdx.x;
    if (c < nfull) {
        // prologue: prefetch depth 2
        issue_chunk(smem_buf, pred4, targ4, c, tid);
        if (c + G < nfull)
            issue_chunk(smem_buf + STAGE_FLOATS, pred4, targ4, c + G, tid);

        int it = 0;
        while (c < nfull) {
            const long long c1 = c + G;
            const long long c2 = c + 2 * G;
            if (c2 < nfull) {
                issue_chunk(smem_buf + ((it + 2) % NSTAGES) * STAGE_FLOATS,
                            pred4, targ4, c2, tid);
            }
            // wait until chunk c's group is complete
            if (c2 < nfull)      asm volatile("cp.async.wait_group 2;");
            else if (c1 < nfull) asm volatile("cp.async.wait_group 1;");
            else                 asm volatile("cp.async.wait_group 0;");
            __syncthreads();   // stage visible to all threads

            const float* stage = smem_buf + (it % NSTAGES) * STAGE_FLOATS;
            acc += cell_loss(stage + tid * 30,
                             stage + FLOATS_PER_CHUNK + tid * 30);

            __syncthreads();   // done reading before this stage is refilled
            c = c1; it++;
        }
    }

    // ragged tail (not hit for benchmark shape): block 0, direct global reads
    if (rem > 0 && blockIdx.x == 0 && tid < rem) {
        const long long cell = (long long)nfull * CPB + tid;
        float Pl[30], Tl[30];
        #pragma unroll
        for (int k = 0; k < 30; k++) {
            Pl[k] = __ldg(pred + cell * 30 + k);
            Tl[k] = __ldg(targ + cell * 30 + k);
        }
        acc += cell_loss(Pl, Tl);
    }

    // block reduction
    #pragma unroll
    for (int o = 16; o > 0; o >>= 1)
        acc += __shfl_down_sync(0xffffffffu, acc, o);
    if ((tid & 31) == 0) warpsum[tid >> 5] = acc;
    __syncthreads();
    if (tid == 0) {
        float s = 0.0f;
        #pragma unroll
        for (int w = 0; w < THREADS / 32; w++) s += warpsum[w];
        g_partials[blockIdx.x] = s;
        __threadfence();
        const unsigned t = atomicAdd(&g_ticket, 1u);
        am_last = (t == gridDim.x - 1);
    }
    __syncthreads();

    // last block reduces all partials in fixed order (deterministic)
    if (am_last) {
        float s = 0.0f;
        for (int i = tid; i < (int)gridDim.x; i += THREADS)
            s += __ldcg(&g_partials[i]);
        #pragma unroll
        for (int o = 16; o > 0; o >>= 1)
            s += __shfl_down_sync(0xffffffffu, s, o);
        if ((tid & 31) == 0) warpsum[tid >> 5] = s;
        __syncthreads();
        if (tid == 0) {
            float tot = 0.0f;
            #pragma unroll
            for (int w = 0; w < THREADS / 32; w++) tot += warpsum[w];
            out[0] = tot * inv_n;
            g_ticket = 0;   // reset for next graph replay
        }
    }
}

extern "C" void kernel_launch(void* const* d_in, const int* in_sizes, int n_in,
                              void* d_out, int out_size)
{
    const float* pred = (const float*)d_in[0];
    const float* targ = (const float*)d_in[1];
    const int total = in_sizes[0];   // N*14*14*30
    const int cells = total / 30;
    const int N = cells / 196;
    const int nfull = cells / CPB;
    const int rem = cells % CPB;

    cudaFuncSetAttribute(yolo_loss_kernel,
                         cudaFuncAttributeMaxDynamicSharedMemorySize, SMEM_BYTES);

    int grid = 148 * 2;              // 2 blocks/SM (92 KB smem each)
    if (grid > nfull) grid = (nfull > 0) ? nfull : 1;
    if (grid > MAX_BLOCKS) grid = MAX_BLOCKS;

    yolo_loss_kernel<<<grid, THREADS, SMEM_BYTES>>>(pred, targ, nfull, rem,
                                                    1.0f / (float)N,
                                                    (float*)d_out);
}

// round 5
// speedup vs baseline: 1.3091x; 1.0231x over previous
#include <cuda_runtime.h>

#define THREADS 128
#define CPB 128                               // cells per chunk
#define FLOATS_PER_CHUNK (CPB * 30)           // 3840
#define VEC_PER_CHUNK (FLOATS_PER_CHUNK / 4)  // 960 float4 per tensor
#define STAGE_FLOATS (2 * FLOATS_PER_CHUNK)   // pred + targ = 7680 floats = 30720 B
#define NSTAGES 3
#define SMEM_BYTES (NSTAGES * STAGE_FLOATS * 4)  // 92160
#define MAX_BLOCKS 4096

__device__ float        g_partials[MAX_BLOCKS];
__device__ unsigned int g_ticket = 0;

extern __shared__ float smem_buf[];

__device__ __forceinline__ void cp16(float* dst, const float4* src) {
    unsigned s = (unsigned)__cvta_generic_to_shared(dst);
    asm volatile("cp.async.cg.shared.global [%0], [%1], 16;" :: "r"(s), "l"(src));
}

// Stage layout: floats [0, 3840) = pred cells, [3840, 7680) = targ cells.
__device__ __forceinline__ void issue_chunk(float* stage,
                                            const float4* __restrict__ pred4,
                                            const float4* __restrict__ targ4,
                                            long long chunk, int tid)
{
    const float4* pb = pred4 + chunk * VEC_PER_CHUNK;
    const float4* tb = targ4 + chunk * VEC_PER_CHUNK;
    #pragma unroll
    for (int m = 0; m < 15; m++) {
        const int idx = tid + m * THREADS;  // 0..1919 exact cover
        const float4* src = (idx < VEC_PER_CHUNK) ? (pb + idx)
                                                  : (tb + (idx - VEC_PER_CHUNK));
        cp16(stage + idx * 4, src);
    }
    asm volatile("cp.async.commit_group;");
}

// Loss from register-resident cell data.
__device__ __forceinline__ float cell_loss_reg(const float* __restrict__ P,
                                               const float* __restrict__ T)
{
    const float inv14 = 1.0f / 14.0f;

    const float conf_t = T[4];
    const float coo = (conf_t > 0.0f) ? 1.0f : 0.0f;
    const float noo = (conf_t == 0.0f) ? 1.0f : 0.0f;

    const float tcx = T[0] * inv14;
    const float tcy = T[1] * inv14;
    const float tx1 = tcx - 0.5f * T[2];
    const float ty1 = tcy - 0.5f * T[3];
    const float tx2 = tcx + 0.5f * T[2];
    const float ty2 = tcy + 0.5f * T[3];
    const float ta = (tx2 - tx1) * (ty2 - ty1);

    float iou[2];
    #pragma unroll
    for (int b = 0; b < 2; b++) {
        const float* B = P + b * 5;
        const float pcx = B[0] * inv14;
        const float pcy = B[1] * inv14;
        const float px1 = pcx - 0.5f * B[2];
        const float py1 = pcy - 0.5f * B[3];
        const float px2 = pcx + 0.5f * B[2];
        const float py2 = pcy + 0.5f * B[3];
        const float ltx = fmaxf(px1, tx1);
        const float lty = fmaxf(py1, ty1);
        const float rbx = fminf(px2, tx2);
        const float rby = fminf(py2, ty2);
        const float w = fmaxf(rbx - ltx, 0.0f);
        const float h = fmaxf(rby - lty, 0.0f);
        const float inter = w * h;
        const float pa = (px2 - px1) * (py2 - py1);
        iou[b] = __fdividef(inter, pa + ta - inter);
    }

    const int r = (iou[1] > iou[0]) ? 1 : 0;   // argmax: first max wins
    const int ro = r * 5, nro = (1 - r) * 5;
    const float max_iou = (iou[1] > iou[0]) ? iou[1] : iou[0];

    const float dx = P[ro + 0] - T[0];
    const float dy = P[ro + 1] - T[1];
    const float dsw = sqrtf(P[ro + 2]) - sqrtf(T[2]);
    const float dsh = sqrtf(P[ro + 3]) - sqrtf(T[3]);
    const float loc = dx * dx + dy * dy + dsw * dsw + dsh * dsh;

    const float dcc = P[ro + 4] - max_iou;
    const float contain = dcc * dcc;
    const float ncl = P[nro + 4] * P[nro + 4];

    const float d4 = P[4] - T[4];
    const float d9 = P[9] - T[9];
    const float noobj = d4 * d4 + d9 * d9;

    float cls = 0.0f;
    #pragma unroll
    for (int k = 10; k < 30; k++) {
        const float d = P[k] - T[k];
        cls += d * d;
    }

    return coo * (5.0f * loc + 2.0f * contain + ncl + cls)
         + 0.5f * noo * noobj;
}

// Pull one cell (30 floats) from smem into registers as 15 back-to-back LDS.64.
__device__ __forceinline__ void load_cell(const float* __restrict__ src30,
                                          float* __restrict__ dst)
{
    const float2* s2 = reinterpret_cast<const float2*>(src30);
    float2 v[15];
    #pragma unroll
    for (int j = 0; j < 15; j++) v[j] = s2[j];
    #pragma unroll
    for (int j = 0; j < 15; j++) { dst[2 * j] = v[j].x; dst[2 * j + 1] = v[j].y; }
}

__global__ void __launch_bounds__(THREADS, 2) yolo_loss_kernel(
    const float* __restrict__ pred,
    const float* __restrict__ targ,
    int nfull, int rem, float inv_n,
    float* __restrict__ out)
{
    __shared__ float warpsum[THREADS / 32];
    __shared__ bool  am_last;

    const int tid = threadIdx.x;
    const long long G = gridDim.x;
    const float4* pred4 = reinterpret_cast<const float4*>(pred);
    const float4* targ4 = reinterpret_cast<const float4*>(targ);

    float acc = 0.0f;

    long long c = blockIdx.x;
    if (c < nfull) {
        issue_chunk(smem_buf, pred4, targ4, c, tid);
        if (c + G < nfull)
            issue_chunk(smem_buf + STAGE_FLOATS, pred4, targ4, c + G, tid);

        int it = 0;
        while (c < nfull) {
            const long long c1 = c + G;
            const long long c2 = c + 2 * G;
            if (c2 < nfull) {
                issue_chunk(smem_buf + ((it + 2) % NSTAGES) * STAGE_FLOATS,
                            pred4, targ4, c2, tid);
            }
            if (c2 < nfull)      asm volatile("cp.async.wait_group 2;");
            else if (c1 < nfull) asm volatile("cp.async.wait_group 1;");
            else                 asm volatile("cp.async.wait_group 0;");
            __syncthreads();

            const float* stage = smem_buf + (it % NSTAGES) * STAGE_FLOATS;

            // Batch-load the whole cell into registers, then compute.
            float Pf[30], Tf[30];
            load_cell(stage + tid * 30, Pf);
            load_cell(stage + FLOATS_PER_CHUNK + tid * 30, Tf);
            acc += cell_loss_reg(Pf, Tf);

            __syncthreads();   // done reading before this stage is refilled
            c = c1; it++;
        }
    }

    // ragged tail (not hit for benchmark shape)
    if (rem > 0 && blockIdx.x == 0 && tid < rem) {
        const long long cell = (long long)nfull * CPB + tid;
        float Pf[30], Tf[30];
        #pragma unroll
        for (int k = 0; k < 30; k++) {
            Pf[k] = __ldg(pred + cell * 30 + k);
            Tf[k] = __ldg(targ + cell * 30 + k);
        }
        acc += cell_loss_reg(Pf, Tf);
    }

    // block reduction
    #pragma unroll
    for (int o = 16; o > 0; o >>= 1)
        acc += __shfl_down_sync(0xffffffffu, acc, o);
    if ((tid & 31) == 0) warpsum[tid >> 5] = acc;
    __syncthreads();
    if (tid == 0) {
        float s = 0.0f;
        #pragma unroll
        for (int w = 0; w < THREADS / 32; w++) s += warpsum[w];
        g_partials[blockIdx.x] = s;
        __threadfence();
        const unsigned t = atomicAdd(&g_ticket, 1u);
        am_last = (t == gridDim.x - 1);
    }
    __syncthreads();

    if (am_last) {
        float s = 0.0f;
        for (int i = tid; i < (int)gridDim.x; i += THREADS)
            s += __ldcg(&g_partials[i]);
        #pragma unroll
        for (int o = 16; o > 0; o >>= 1)
            s += __shfl_down_sync(0xffffffffu, s, o);
        if ((tid & 31) == 0) warpsum[tid >> 5] = s;
        __syncthreads();
        if (tid == 0) {
            float tot = 0.0f;
            #pragma unroll
            for (int w = 0; w < THREADS / 32; w++) tot += warpsum[w];
            out[0] = tot * inv_n;
            g_ticket = 0;   // reset for next graph replay
        }
    }
}

extern "C" void kernel_launch(void* const* d_in, const int* in_sizes, int n_in,
                              void* d_out, int out_size)
{
    const float* pred = (const float*)d_in[0];
    const float* targ = (const float*)d_in[1];
    const int total = in_sizes[0];   // N*14*14*30
    const int cells = total / 30;
    const int N = cells / 196;
    const int nfull = cells / CPB;
    const int rem = cells % CPB;

    cudaFuncSetAttribute(yolo_loss_kernel,
                         cudaFuncAttributeMaxDynamicSharedMemorySize, SMEM_BYTES);

    int grid = 148 * 2;              // 2 blocks/SM (92 KB smem each)
    if (grid > nfull) grid = (nfull > 0) ? nfull : 1;
    if (grid > MAX_BLOCKS) grid = MAX_BLOCKS;

    yolo_loss_kernel<<<grid, THREADS, SMEM_BYTES>>>(pred, targ, nfull, rem,
                                                    1.0f / (float)N,
                                                    (float*)d_out);
}

// round 6
// speedup vs baseline: 1.3261x; 1.0130x over previous
#include <cuda_runtime.h>
#include <cstdint>

#define THREADS 256
#define CPB 256                                   // cells per chunk
#define TENSOR_CHUNK_BYTES (CPB * 30 * 4)         // 30720
#define STAGE_BYTES (2 * TENSOR_CHUNK_BYTES)      // 61440 (pred + targ)
#define STAGE_FLOATS (STAGE_BYTES / 4)            // 15360
#define TENSOR_CHUNK_FLOATS (TENSOR_CHUNK_BYTES / 4) // 7680
#define NSTAGES 3
#define SMEM_BYTES (NSTAGES * STAGE_BYTES)        // 184320
#define MAX_BLOCKS 4096

__device__ float        g_partials[MAX_BLOCKS];
__device__ unsigned int g_ticket = 0;

extern __shared__ float smem_buf[];

__device__ __forceinline__ uint32_t smem_u32(const void* p) {
    return (uint32_t)__cvta_generic_to_shared(p);
}

__device__ __forceinline__ void mbar_init(uint32_t bar, uint32_t count) {
    asm volatile("mbarrier.init.shared.b64 [%0], %1;" :: "r"(bar), "r"(count) : "memory");
}
__device__ __forceinline__ void mbar_expect_tx(uint32_t bar, uint32_t bytes) {
    asm volatile("mbarrier.arrive.expect_tx.shared.b64 _, [%0], %1;"
                 :: "r"(bar), "r"(bytes) : "memory");
}
__device__ __forceinline__ void mbar_wait(uint32_t bar, uint32_t phase) {
    uint32_t done;
    asm volatile(
        "{\n\t.reg .pred p;\n\t"
        "mbarrier.try_wait.parity.acquire.cta.shared::cta.b64 p, [%1], %2;\n\t"
        "selp.b32 %0, 1, 0, p;\n\t}"
        : "=r"(done) : "r"(bar), "r"(phase) : "memory");
    while (!done) {
        asm volatile(
            "{\n\t.reg .pred p;\n\t"
            "mbarrier.try_wait.parity.acquire.cta.shared::cta.b64 p, [%1], %2, 0x989680;\n\t"
            "selp.b32 %0, 1, 0, p;\n\t}"
            : "=r"(done) : "r"(bar), "r"(phase) : "memory");
    }
}
// Bulk async copy global -> shared, completion via mbarrier complete_tx.
__device__ __forceinline__ void bulk_cp(uint32_t dst_smem, const void* src_gmem,
                                        uint32_t bytes, uint32_t bar) {
    asm volatile(
        "cp.async.bulk.shared::cluster.global.mbarrier::complete_tx::bytes "
        "[%0], [%1], %2, [%3];"
        :: "r"(dst_smem), "l"(src_gmem), "r"(bytes), "r"(bar) : "memory");
}

// Loss from register-resident cell data.
__device__ __forceinline__ float cell_loss_reg(const float* __restrict__ P,
                                               const float* __restrict__ T)
{
    const float inv14 = 1.0f / 14.0f;

    const float conf_t = T[4];
    const float coo = (conf_t > 0.0f) ? 1.0f : 0.0f;
    const float noo = (conf_t == 0.0f) ? 1.0f : 0.0f;

    const float tcx = T[0] * inv14;
    const float tcy = T[1] * inv14;
    const float tx1 = tcx - 0.5f * T[2];
    const float ty1 = tcy - 0.5f * T[3];
    const float tx2 = tcx + 0.5f * T[2];
    const float ty2 = tcy + 0.5f * T[3];
    const float ta = (tx2 - tx1) * (ty2 - ty1);

    float iou[2];
    #pragma unroll
    for (int b = 0; b < 2; b++) {
        const float* B = P + b * 5;
        const float pcx = B[0] * inv14;
        const float pcy = B[1] * inv14;
        const float px1 = pcx - 0.5f * B[2];
        const float py1 = pcy - 0.5f * B[3];
        const float px2 = pcx + 0.5f * B[2];
        const float py2 = pcy + 0.5f * B[3];
        const float ltx = fmaxf(px1, tx1);
        const float lty = fmaxf(py1, ty1);
        const float rbx = fminf(px2, tx2);
        const float rby = fminf(py2, ty2);
        const float w = fmaxf(rbx - ltx, 0.0f);
        const float h = fmaxf(rby - lty, 0.0f);
        const float inter = w * h;
        const float pa = (px2 - px1) * (py2 - py1);
        iou[b] = __fdividef(inter, pa + ta - inter);
    }

    const int r = (iou[1] > iou[0]) ? 1 : 0;   // argmax: first max wins
    const int ro = r * 5, nro = (1 - r) * 5;
    const float max_iou = (iou[1] > iou[0]) ? iou[1] : iou[0];

    const float dx = P[ro + 0] - T[0];
    const float dy = P[ro + 1] - T[1];
    const float dsw = sqrtf(P[ro + 2]) - sqrtf(T[2]);
    const float dsh = sqrtf(P[ro + 3]) - sqrtf(T[3]);
    const float loc = dx * dx + dy * dy + dsw * dsw + dsh * dsh;

    const float dcc = P[ro + 4] - max_iou;
    const float contain = dcc * dcc;
    const float ncl = P[nro + 4] * P[nro + 4];

    const float d4 = P[4] - T[4];
    const float d9 = P[9] - T[9];
    const float noobj = d4 * d4 + d9 * d9;

    float cls = 0.0f;
    #pragma unroll
    for (int k = 10; k < 30; k++) {
        const float d = P[k] - T[k];
        cls += d * d;
    }

    return coo * (5.0f * loc + 2.0f * contain + ncl + cls)
         + 0.5f * noo * noobj;
}

// Pull one cell (30 floats) from smem into registers: 15 back-to-back LDS.64.
__device__ __forceinline__ void load_cell(const float* __restrict__ src30,
                                          float* __restrict__ dst)
{
    const float2* s2 = reinterpret_cast<const float2*>(src30);
    float2 v[15];
    #pragma unroll
    for (int j = 0; j < 15; j++) v[j] = s2[j];
    #pragma unroll
    for (int j = 0; j < 15; j++) { dst[2 * j] = v[j].x; dst[2 * j + 1] = v[j].y; }
}

__global__ void __launch_bounds__(THREADS, 1) yolo_loss_kernel(
    const float* __restrict__ pred,
    const float* __restrict__ targ,
    int nfull, int rem, float inv_n,
    float* __restrict__ out)
{
    __shared__ __align__(8) unsigned long long mbar_storage[NSTAGES];
    __shared__ float warpsum[THREADS / 32];
    __shared__ bool  am_last;

    const int tid = threadIdx.x;
    const long long G = gridDim.x;
    const char* pbytes = reinterpret_cast<const char*>(pred);
    const char* tbytes = reinterpret_cast<const char*>(targ);

    uint32_t bar[NSTAGES];
    #pragma unroll
    for (int s = 0; s < NSTAGES; s++) bar[s] = smem_u32(&mbar_storage[s]);
    const uint32_t stage0 = smem_u32(smem_buf);

    if (tid == 0) {
        #pragma unroll
        for (int s = 0; s < NSTAGES; s++) mbar_init(bar[s], 1);
    }
    __syncthreads();

    float acc = 0.0f;
    long long c = blockIdx.x;

    if (c < nfull) {
        // prologue: stages 0 and 1
        if (tid == 0) {
            mbar_expect_tx(bar[0], STAGE_BYTES);
            bulk_cp(stage0, pbytes + c * TENSOR_CHUNK_BYTES, TENSOR_CHUNK_BYTES, bar[0]);
            bulk_cp(stage0 + TENSOR_CHUNK_BYTES, tbytes + c * TENSOR_CHUNK_BYTES,
                    TENSOR_CHUNK_BYTES, bar[0]);
            if (c + G < nfull) {
                mbar_expect_tx(bar[1], STAGE_BYTES);
                bulk_cp(stage0 + STAGE_BYTES, pbytes + (c + G) * TENSOR_CHUNK_BYTES,
                        TENSOR_CHUNK_BYTES, bar[1]);
                bulk_cp(stage0 + STAGE_BYTES + TENSOR_CHUNK_BYTES,
                        tbytes + (c + G) * TENSOR_CHUNK_BYTES,
                        TENSOR_CHUNK_BYTES, bar[1]);
            }
        }

        int it = 0;
        while (c < nfull) {
            const long long c2 = c + 2 * G;
            const int s2 = (it + 2) % NSTAGES;   // stage consumed at it-1; safe after
                                                 // the syncthreads that ended iter it-1
            if (c2 < nfull && tid == 0) {
                mbar_expect_tx(bar[s2], STAGE_BYTES);
                const uint32_t dst = stage0 + s2 * STAGE_BYTES;
                bulk_cp(dst, pbytes + c2 * TENSOR_CHUNK_BYTES, TENSOR_CHUNK_BYTES, bar[s2]);
                bulk_cp(dst + TENSOR_CHUNK_BYTES, tbytes + c2 * TENSOR_CHUNK_BYTES,
                        TENSOR_CHUNK_BYTES, bar[s2]);
            }

            const int s = it % NSTAGES;
            mbar_wait(bar[s], (it / NSTAGES) & 1);

            const float* stage = smem_buf + s * STAGE_FLOATS;
            float Pf[30], Tf[30];
            load_cell(stage + tid * 30, Pf);
            load_cell(stage + TENSOR_CHUNK_FLOATS + tid * 30, Tf);
            acc += cell_loss_reg(Pf, Tf);

            __syncthreads();   // all threads done reading stage s before it is reissued
            c += G; it++;
        }
    }

    // ragged tail (not hit for the benchmark shape)
    if (rem > 0 && blockIdx.x == 0 && tid < rem) {
        const long long cell = (long long)nfull * CPB + tid;
        float Pf[30], Tf[30];
        #pragma unroll
        for (int k = 0; k < 30; k++) {
            Pf[k] = __ldg(pred + cell * 30 + k);
            Tf[k] = __ldg(targ + cell * 30 + k);
        }
        acc += cell_loss_reg(Pf, Tf);
    }

    // block reduction
    #pragma unroll
    for (int o = 16; o > 0; o >>= 1)
        acc += __shfl_down_sync(0xffffffffu, acc, o);
    if ((tid & 31) == 0) warpsum[tid >> 5] = acc;
    __syncthreads();
    if (tid == 0) {
        float s = 0.0f;
        #pragma unroll
        for (int w = 0; w < THREADS / 32; w++) s += warpsum[w];
        g_partials[blockIdx.x] = s;
        __threadfence();
        const unsigned t = atomicAdd(&g_ticket, 1u);
        am_last = (t == gridDim.x - 1);
    }
    __syncthreads();

    // last block reduces all partials in fixed order (deterministic)
    if (am_last) {
        float s = 0.0f;
        for (int i = tid; i < (int)gridDim.x; i += THREADS)
            s += __ldcg(&g_partials[i]);
        #pragma unroll
        for (int o = 16; o > 0; o >>= 1)
            s += __shfl_down_sync(0xffffffffu, s, o);
        if ((tid & 31) == 0) warpsum[tid >> 5] = s;
        __syncthreads();
        if (tid == 0) {
            float tot = 0.0f;
            #pragma unroll
            for (int w = 0; w < THREADS / 32; w++) tot += warpsum[w];
            out[0] = tot * inv_n;
            g_ticket = 0;   // reset for next graph replay
        }
    }
}

extern "C" void kernel_launch(void* const* d_in, const int* in_sizes, int n_in,
                              void* d_out, int out_size)
{
    const float* pred = (const float*)d_in[0];
    const float* targ = (const float*)d_in[1];
    const int total = in_sizes[0];   // N*14*14*30
    const int cells = total / 30;
    const int N = cells / 196;
    const int nfull = cells / CPB;
    const int rem = cells % CPB;

    cudaFuncSetAttribute(yolo_loss_kernel,
                         cudaFuncAttributeMaxDynamicSharedMemorySize, SMEM_BYTES);

    int sms = 148;
    cudaDeviceGetAttribute(&sms, cudaDevAttrMultiProcessorCount, 0);

    int grid = sms;                  // 1 block/SM (184 KB smem each)
    if (grid > nfull) grid = (nfull > 0) ? nfull : 1;
    if (grid > MAX_BLOCKS) grid = MAX_BLOCKS;

    yolo_loss_kernel<<<grid, THREADS, SMEM_BYTES>>>(pred, targ, nfull, rem,
                                                    1.0f / (float)N,
                                                    (float*)d_out);
}